// round 4
// baseline (speedup 1.0000x reference)
#include <cuda_runtime.h>
#include <cstdint>

#define N_NODES 100000
#define N_EDGES 1600000
#define HID     128
#define NH      12800000      // N_NODES * HID

// ---------------- scratch (__device__ globals: no runtime allocation) -------
__device__ float g_dinv[N_NODES];   // deg -> dinv in place
__device__ float g_agg[NH];         // aggregation buffer (A@x, then A@h1)
__device__ float g_h1[NH];          // hidden after conv1
__device__ float g_mu[NH];          // fallback scratch if out_size < 3*NH
__device__ float g_lv[NH];

// ---------------- small elementwise kernels --------------------------------
__global__ void k_zero_deg() {
    int i = blockIdx.x * 256 + threadIdx.x;
    if (i < N_NODES) g_dinv[i] = 0.0f;
}

__global__ void k_degree(const int* __restrict__ dst) {
    int i = blockIdx.x * 256 + threadIdx.x;
    if (i < N_EDGES) atomicAdd(&g_dinv[dst[i]], 1.0f);
}

__global__ void k_dinv() {
    int i = blockIdx.x * 256 + threadIdx.x;
    if (i < N_NODES) g_dinv[i] = 1.0f / sqrtf(g_dinv[i] + 1.0f);
}

// agg = feat * self_coef (self-loop term); atomics add neighbor messages on top
__global__ void k_self_init(const float* __restrict__ feat, float* __restrict__ agg) {
    int i = blockIdx.x * 256 + threadIdx.x;   // float4 index
    if (i >= NH / 4) return;
    int n = i >> 5;                           // 32 float4 per node row
    float di = g_dinv[n];
    float sc = di * di;
    float4 v = ((const float4*)feat)[i];
    v.x *= sc; v.y *= sc; v.z *= sc; v.w *= sc;
    ((float4*)agg)[i] = v;
}

// one warp per edge; lane handles 4 floats -> fully coalesced 512B row gather
// + vector reduction (red.global.add.v4.f32, sm_90+)
__global__ void k_scatter(const float* __restrict__ feat, float* __restrict__ agg,
                          const int* __restrict__ src, const int* __restrict__ dst) {
    int t = blockIdx.x * 256 + threadIdx.x;
    int e = t >> 5;
    int lane = t & 31;
    if (e >= N_EDGES) return;
    int s = src[e];
    int d = dst[e];
    float c = g_dinv[s] * g_dinv[d];
    float4 v = *(const float4*)(feat + (size_t)s * HID + lane * 4);
    float* p = agg + (size_t)d * HID + lane * 4;
    asm volatile("red.global.add.v4.f32 [%0], {%1,%2,%3,%4};"
                 :: "l"(p), "f"(v.x * c), "f"(v.y * c), "f"(v.z * c), "f"(v.w * c)
                 : "memory");
}

// ---------------- fp32 GEMM: C[M,128] = A[M,128] @ W[128,128] + b ----------
// 128-row tile per block, W fully resident in smem, 8x8 register micro-tile.
// act: 0 = none, 1 = ELU
__global__ __launch_bounds__(256) void k_gemm(const float* __restrict__ A,
                                              const float* __restrict__ W,
                                              const float* __restrict__ bias,
                                              float* __restrict__ C,
                                              int act) {
    extern __shared__ float sm[];
    float* xs = sm;                 // transposed A tile: xs[k*132 + r], k,r in [0,128)
    float* ws = sm + 128 * 132;     // W row-major: ws[k*128 + c]

    int row0 = blockIdx.x << 7;

    // load A tile transposed (lane-consecutive rows -> conflict-free smem writes)
    for (int i = threadIdx.x; i < 4096; i += 256) {
        int r  = i & 127;
        int c4 = i >> 7;            // 0..31
        float4 v = make_float4(0.f, 0.f, 0.f, 0.f);
        if (row0 + r < N_NODES)
            v = *(const float4*)(A + (size_t)(row0 + r) * HID + (c4 << 2));
        int k = c4 << 2;
        xs[(k + 0) * 132 + r] = v.x;
        xs[(k + 1) * 132 + r] = v.y;
        xs[(k + 2) * 132 + r] = v.z;
        xs[(k + 3) * 132 + r] = v.w;
    }
    // copy W (contiguous float4, coalesced + conflict-free)
    for (int i = threadIdx.x; i < 4096; i += 256) {
        *(float4*)(ws + (i << 2)) = *(const float4*)(W + (i << 2));
    }
    __syncthreads();

    int tx = threadIdx.x & 15;
    int ty = threadIdx.x >> 4;
    int r0 = ty << 3;
    int c0 = tx << 3;

    float acc[8][8];
#pragma unroll
    for (int i = 0; i < 8; i++)
#pragma unroll
        for (int j = 0; j < 8; j++) acc[i][j] = 0.f;

#pragma unroll 4
    for (int k = 0; k < 128; k++) {
        float a[8], w[8];
        *(float4*)(a)     = *(float4*)(xs + k * 132 + r0);
        *(float4*)(a + 4) = *(float4*)(xs + k * 132 + r0 + 4);
        *(float4*)(w)     = *(float4*)(ws + (k << 7) + c0);
        *(float4*)(w + 4) = *(float4*)(ws + (k << 7) + c0 + 4);
#pragma unroll
        for (int i = 0; i < 8; i++)
#pragma unroll
            for (int j = 0; j < 8; j++)
                acc[i][j] = fmaf(a[i], w[j], acc[i][j]);
    }

    float bv[8];
    *(float4*)(bv)     = *(const float4*)(bias + c0);
    *(float4*)(bv + 4) = *(const float4*)(bias + c0 + 4);

#pragma unroll
    for (int i = 0; i < 8; i++) {
        int r = row0 + r0 + i;
        if (r >= N_NODES) break;
        float o[8];
#pragma unroll
        for (int j = 0; j < 8; j++) {
            float v = acc[i][j] + bv[j];
            if (act) v = (v > 0.f) ? v : expm1f(v);   // ELU(alpha=1)
            o[j] = v;
        }
        *(float4*)(C + (size_t)r * HID + c0)     = *(float4*)(o);
        *(float4*)(C + (size_t)r * HID + c0 + 4) = *(float4*)(o + 4);
    }
}

// ------- JAX-exact RNG: PARTITIONABLE threefry2x32 + XLA erfinv ------------
// jax_threefry_partitionable defaults to True (JAX >= 0.4.30):
//   counts = iota(uint64, size);  x0 = counts >> 32 (=0 here), x1 = low 32
//   bits1, bits2 = threefry2x32(key, x0, x1);  bits = bits1 ^ bits2
__device__ __forceinline__ uint32_t rotl32(uint32_t x, int d) {
    return (x << d) | (x >> (32 - d));
}

// key = jax.random.key(42) -> (k0,k1) = (0, 42)
__device__ __forceinline__ uint32_t threefry_bits_0_42(uint32_t x0, uint32_t x1) {
    const uint32_t k0 = 0u, k1 = 42u;
    const uint32_t k2 = k0 ^ k1 ^ 0x1BD11BDAu;
    x0 += k0; x1 += k1;
#define TF_RND(r) { x0 += x1; x1 = rotl32(x1, r); x1 ^= x0; }
    TF_RND(13) TF_RND(15) TF_RND(26) TF_RND(6)
    x0 += k1; x1 += k2 + 1u;
    TF_RND(17) TF_RND(29) TF_RND(16) TF_RND(24)
    x0 += k2; x1 += k0 + 2u;
    TF_RND(13) TF_RND(15) TF_RND(26) TF_RND(6)
    x0 += k0; x1 += k1 + 3u;
    TF_RND(17) TF_RND(29) TF_RND(16) TF_RND(24)
    x0 += k1; x1 += k2 + 4u;
    TF_RND(13) TF_RND(15) TF_RND(26) TF_RND(6)
    x0 += k2; x1 += k0 + 5u;
#undef TF_RND
    return x0 ^ x1;      // 32-bit XOR-fold (partitionable path)
}

// XLA ErfInv fp32 (Giles polynomial) — matches jax.lax.erf_inv on f32
__device__ __forceinline__ float erfinv_xla(float x) {
    float w = -log1pf(-x * x);
    float p;
    if (w < 5.0f) {
        w -= 2.5f;
        p = 2.81022636e-08f;
        p = fmaf(p, w, 3.43273939e-07f);
        p = fmaf(p, w, -3.5233877e-06f);
        p = fmaf(p, w, -4.39150654e-06f);
        p = fmaf(p, w, 0.00021858087f);
        p = fmaf(p, w, -0.00125372503f);
        p = fmaf(p, w, -0.00417768164f);
        p = fmaf(p, w, 0.246640727f);
        p = fmaf(p, w, 1.50140941f);
    } else {
        w = sqrtf(w) - 3.0f;
        p = -0.000200214257f;
        p = fmaf(p, w, 0.000100950558f);
        p = fmaf(p, w, 0.00134934322f);
        p = fmaf(p, w, -0.00367342844f);
        p = fmaf(p, w, 0.00573950773f);
        p = fmaf(p, w, -0.0076224613f);
        p = fmaf(p, w, 0.00943887047f);
        p = fmaf(p, w, 1.00167406f);
        p = fmaf(p, w, 2.83297682f);
    }
    return p * x;
}

__device__ __forceinline__ float bits_to_normal(uint32_t bits) {
    // uniform in [lo, 1): u01 = bitcast((bits>>9)|0x3f800000) - 1  in [0,1)
    float u01 = __uint_as_float((bits >> 9) | 0x3f800000u) - 1.0f;
    const float lo = -0.99999994f;           // nextafter(-1, 0)
    float u = fmaf(u01, 2.0f, lo);           // (1 - lo) rounds to 2.0f in fp32
    u = fmaxf(u, lo);
    return 1.41421356237f * erfinv_xla(u);   // sqrt(2) * erfinv
}

// z = mu + eps * exp(0.5*logvar); one element per thread, counter = (0, i)
__global__ void k_reparam(float* __restrict__ z,
                          const float* __restrict__ mu,
                          const float* __restrict__ lv) {
    int i = blockIdx.x * 256 + threadIdx.x;
    if (i >= NH) return;
    uint32_t bits = threefry_bits_0_42(0u, (uint32_t)i);
    float eps = bits_to_normal(bits);
    z[i] = mu[i] + eps * expf(0.5f * lv[i]);
}

// ---------------- launch ---------------------------------------------------
extern "C" void kernel_launch(void* const* d_in, const int* in_sizes, int n_in,
                              void* d_out, int out_size) {
    const float* x   = (const float*)d_in[0];
    const int*   ei  = (const int*)d_in[1];
    const float* W1  = (const float*)d_in[2];
    const float* b1  = (const float*)d_in[3];
    const float* Wmu = (const float*)d_in[4];
    const float* bmu = (const float*)d_in[5];
    const float* Wlv = (const float*)d_in[6];
    const float* blv = (const float*)d_in[7];
    float* out = (float*)d_out;

    const int* src = ei;
    const int* dst = ei + N_EDGES;

    void *p_agg, *p_h1, *p_mu, *p_lv;
    cudaGetSymbolAddress(&p_agg, g_agg);
    cudaGetSymbolAddress(&p_h1,  g_h1);
    cudaGetSymbolAddress(&p_mu,  g_mu);
    cudaGetSymbolAddress(&p_lv,  g_lv);

    // output layout: [z | mu | logvar] when out_size allows; else scratch
    float* mu_dst = (out_size >= 3 * NH) ? (out + NH)     : (float*)p_mu;
    float* lv_dst = (out_size >= 3 * NH) ? (out + 2 * NH) : (float*)p_lv;

    const size_t gemm_smem = (128 * 132 + 128 * 128) * sizeof(float);  // 133,120 B
    cudaFuncSetAttribute(k_gemm, cudaFuncAttributeMaxDynamicSharedMemorySize,
                         (int)gemm_smem);

    const int nb_nodes = (N_NODES + 255) / 256;          // 391
    const int nb_edges = (N_EDGES + 255) / 256;          // 6250
    const int nb_feat4 = (NH / 4 + 255) / 256;           // 12500
    const int nb_scat  = (N_EDGES * 32) / 256;           // 200000
    const int nb_gemm  = (N_NODES + 127) / 128;          // 782
    const int nb_rep   = (NH + 255) / 256;               // 50000

    // degree -> dinv
    k_zero_deg<<<nb_nodes, 256>>>();
    k_degree<<<nb_edges, 256>>>(dst);
    k_dinv<<<nb_nodes, 256>>>();

    // layer 1: agg = A_norm @ x ; h1 = elu(agg @ W1 + b1)
    k_self_init<<<nb_feat4, 256>>>(x, (float*)p_agg);
    k_scatter<<<nb_scat, 256>>>(x, (float*)p_agg, src, dst);
    k_gemm<<<nb_gemm, 256, gemm_smem>>>((const float*)p_agg, W1, b1, (float*)p_h1, 1);

    // layer 2: agg = A_norm @ h1 ; mu = agg@Wmu+bmu ; lv = agg@Wlv+blv
    k_self_init<<<nb_feat4, 256>>>((const float*)p_h1, (float*)p_agg);
    k_scatter<<<nb_scat, 256>>>((const float*)p_h1, (float*)p_agg, src, dst);
    k_gemm<<<nb_gemm, 256, gemm_smem>>>((const float*)p_agg, Wmu, bmu, mu_dst, 0);
    k_gemm<<<nb_gemm, 256, gemm_smem>>>((const float*)p_agg, Wlv, blv, lv_dst, 0);

    // reparameterize (JAX partitionable threefry, key 42)
    k_reparam<<<nb_rep, 256>>>(out, mu_dst, lv_dst);
}

// round 5
// speedup vs baseline: 1.0019x; 1.0019x over previous
#include <cuda_runtime.h>
#include <cstdint>

#define N_NODES 100000
#define N_EDGES 1600000
#define HID     128
#define NH      12800000      // N_NODES * HID
#define NB_SCAN 391           // ceil(N_NODES/256)

typedef unsigned long long u64;

// ---------------- scratch (__device__ globals: no runtime allocation) -------
__device__ float g_dinv[N_NODES];
__device__ int   g_cnt[N_NODES];
__device__ int   g_rowptr[N_NODES + 1];
__device__ int   g_cursor[N_NODES];
__device__ int   g_col[N_EDGES];
__device__ float g_coef[N_EDGES];
__device__ int   g_bsum[512];
__device__ int   g_boff[512];
__device__ float g_agg[NH];
__device__ float g_h1[NH];
__device__ float g_mu[NH];
__device__ float g_lv[NH];

// ---------------- degree / norm --------------------------------------------
__global__ void k_zero_cnt() {
    int i = blockIdx.x * 256 + threadIdx.x;
    if (i < N_NODES) g_cnt[i] = 0;
}
__global__ void k_degree(const int* __restrict__ dst) {
    int i = blockIdx.x * 256 + threadIdx.x;
    if (i < N_EDGES) atomicAdd(&g_cnt[dst[i]], 1);
}
__global__ void k_dinv() {
    int i = blockIdx.x * 256 + threadIdx.x;
    if (i < N_NODES) g_dinv[i] = rsqrtf((float)g_cnt[i] + 1.0f);
}

// ---------------- CSR build: scan + fill ------------------------------------
__global__ void k_scan1() {
    __shared__ int sh[256];
    int tid = threadIdx.x;
    int i = blockIdx.x * 256 + tid;
    int v = (i < N_NODES) ? g_cnt[i] : 0;
    sh[tid] = v;
    __syncthreads();
#pragma unroll
    for (int off = 1; off < 256; off <<= 1) {
        int t = (tid >= off) ? sh[tid - off] : 0;
        __syncthreads();
        sh[tid] += t;
        __syncthreads();
    }
    if (i < N_NODES) g_rowptr[i] = sh[tid] - v;      // block-local exclusive
    if (tid == 255) g_bsum[blockIdx.x] = sh[255];
}
__global__ void k_scan2() {   // single block, 512 threads
    __shared__ int sh[512];
    int tid = threadIdx.x;
    int v = (tid < NB_SCAN) ? g_bsum[tid] : 0;
    sh[tid] = v;
    __syncthreads();
#pragma unroll
    for (int off = 1; off < 512; off <<= 1) {
        int t = (tid >= off) ? sh[tid - off] : 0;
        __syncthreads();
        sh[tid] += t;
        __syncthreads();
    }
    g_boff[tid] = sh[tid] - v;                        // exclusive block offsets
    if (tid == 0) g_rowptr[N_NODES] = N_EDGES;
}
__global__ void k_scan3() {
    int i = blockIdx.x * 256 + threadIdx.x;
    if (i < N_NODES) {
        int r = g_rowptr[i] + g_boff[i >> 8];
        g_rowptr[i] = r;
        g_cursor[i] = r;
    }
}
__global__ void k_fill(const int* __restrict__ src, const int* __restrict__ dst) {
    int e = blockIdx.x * 256 + threadIdx.x;
    if (e >= N_EDGES) return;
    int d = dst[e], s = src[e];
    int pos = atomicAdd(&g_cursor[d], 1);
    g_col[pos]  = s;
    g_coef[pos] = g_dinv[s] * g_dinv[d];
}

// ---------------- CSR aggregation: agg = A_norm @ feat  (no atomics) --------
// one warp per node; lane owns 4 contiguous floats (float4) of the 128-row
__global__ __launch_bounds__(256) void k_agg(const float* __restrict__ feat,
                                             float* __restrict__ agg) {
    int w    = (blockIdx.x * 256 + threadIdx.x) >> 5;
    int lane = threadIdx.x & 31;
    if (w >= N_NODES) return;
    int beg = g_rowptr[w];
    int end = g_rowptr[w + 1];
    float di = g_dinv[w];
    float sc = di * di;

    const float* frow = feat + (size_t)w * HID + lane * 4;
    float4 acc = *(const float4*)frow;
    acc.x *= sc; acc.y *= sc; acc.z *= sc; acc.w *= sc;

    int j = beg;
    for (; j + 1 < end; j += 2) {
        int   s0 = g_col[j],     s1 = g_col[j + 1];
        float c0 = g_coef[j],    c1 = g_coef[j + 1];
        float4 v0 = *(const float4*)(feat + (size_t)s0 * HID + lane * 4);
        float4 v1 = *(const float4*)(feat + (size_t)s1 * HID + lane * 4);
        acc.x = fmaf(c0, v0.x, acc.x); acc.y = fmaf(c0, v0.y, acc.y);
        acc.z = fmaf(c0, v0.z, acc.z); acc.w = fmaf(c0, v0.w, acc.w);
        acc.x = fmaf(c1, v1.x, acc.x); acc.y = fmaf(c1, v1.y, acc.y);
        acc.z = fmaf(c1, v1.z, acc.z); acc.w = fmaf(c1, v1.w, acc.w);
    }
    if (j < end) {
        int   s0 = g_col[j];
        float c0 = g_coef[j];
        float4 v0 = *(const float4*)(feat + (size_t)s0 * HID + lane * 4);
        acc.x = fmaf(c0, v0.x, acc.x); acc.y = fmaf(c0, v0.y, acc.y);
        acc.z = fmaf(c0, v0.z, acc.z); acc.w = fmaf(c0, v0.w, acc.w);
    }
    *(float4*)(agg + (size_t)w * HID + lane * 4) = acc;
}

// ---------------- packed f32x2 GEMM -----------------------------------------
// C[M,128] = A[M,128] @ W[128,128] + b, optional ELU, optional fused reparam.
// A tile transposed in smem (float, stride 132); W duplicated-pair smem (u64).
// Thread micro-tile: row-pairs p(i2)=ty+16*i2 (rows 2p,2p+1), cols c(jj)=tx+16*jj.
// All LDS.64 are bank-conflict-free by construction.
__device__ __forceinline__ u64 fma2(u64 a, u64 b, u64 c) {
    u64 d;
    asm("fma.rn.f32x2 %0, %1, %2, %3;" : "=l"(d) : "l"(a), "l"(b), "l"(c));
    return d;
}
__device__ __forceinline__ u64 add2(u64 a, u64 b) {
    u64 d;
    asm("add.rn.f32x2 %0, %1, %2;" : "=l"(d) : "l"(a), "l"(b));
    return d;
}
__device__ __forceinline__ u64 dup2(float f) {
    unsigned u = __float_as_uint(f);
    return ((u64)u << 32) | u;
}

// ------- JAX-exact RNG: PARTITIONABLE threefry2x32 + XLA erfinv -------------
__device__ __forceinline__ uint32_t rotl32(uint32_t x, int d) {
    return (x << d) | (x >> (32 - d));
}
__device__ __forceinline__ uint32_t threefry_bits_0_42(uint32_t x0, uint32_t x1) {
    const uint32_t k0 = 0u, k1 = 42u;
    const uint32_t k2 = k0 ^ k1 ^ 0x1BD11BDAu;
    x0 += k0; x1 += k1;
#define TF_RND(r) { x0 += x1; x1 = rotl32(x1, r); x1 ^= x0; }
    TF_RND(13) TF_RND(15) TF_RND(26) TF_RND(6)
    x0 += k1; x1 += k2 + 1u;
    TF_RND(17) TF_RND(29) TF_RND(16) TF_RND(24)
    x0 += k2; x1 += k0 + 2u;
    TF_RND(13) TF_RND(15) TF_RND(26) TF_RND(6)
    x0 += k0; x1 += k1 + 3u;
    TF_RND(17) TF_RND(29) TF_RND(16) TF_RND(24)
    x0 += k1; x1 += k2 + 4u;
    TF_RND(13) TF_RND(15) TF_RND(26) TF_RND(6)
    x0 += k2; x1 += k0 + 5u;
#undef TF_RND
    return x0 ^ x1;      // 32-bit XOR-fold (partitionable path)
}
__device__ __forceinline__ float erfinv_xla(float x) {
    float w = -log1pf(-x * x);
    float p;
    if (w < 5.0f) {
        w -= 2.5f;
        p = 2.81022636e-08f;
        p = fmaf(p, w, 3.43273939e-07f);
        p = fmaf(p, w, -3.5233877e-06f);
        p = fmaf(p, w, -4.39150654e-06f);
        p = fmaf(p, w, 0.00021858087f);
        p = fmaf(p, w, -0.00125372503f);
        p = fmaf(p, w, -0.00417768164f);
        p = fmaf(p, w, 0.246640727f);
        p = fmaf(p, w, 1.50140941f);
    } else {
        w = sqrtf(w) - 3.0f;
        p = -0.000200214257f;
        p = fmaf(p, w, 0.000100950558f);
        p = fmaf(p, w, 0.00134934322f);
        p = fmaf(p, w, -0.00367342844f);
        p = fmaf(p, w, 0.00573950773f);
        p = fmaf(p, w, -0.0076224613f);
        p = fmaf(p, w, 0.00943887047f);
        p = fmaf(p, w, 1.00167406f);
        p = fmaf(p, w, 2.83297682f);
    }
    return p * x;
}
__device__ __forceinline__ float bits_to_normal(uint32_t bits) {
    float u01 = __uint_as_float((bits >> 9) | 0x3f800000u) - 1.0f;
    const float lo = -0.99999994f;
    float u = fmaf(u01, 2.0f, lo);
    u = fmaxf(u, lo);
    return 1.41421356237f * erfinv_xla(u);
}

// act: 1 = ELU. do_rep: 1 = also compute z = mu + eps*exp(0.5*C) into z_out.
__global__ __launch_bounds__(256) void k_gemm2(const float* __restrict__ A,
                                               const float* __restrict__ W,
                                               const float* __restrict__ bias,
                                               float* __restrict__ C,
                                               const float* __restrict__ mu_in,
                                               float* __restrict__ z_out,
                                               int act, int do_rep) {
    extern __shared__ float sm[];
    float* xs = sm;                              // [k*132 + r], 128x128 (+pad)
    u64*   wd = (u64*)(sm + 128 * 132);          // [k*128 + c] duplicated pairs

    int row0 = blockIdx.x << 7;

    // A tile transposed
    for (int i = threadIdx.x; i < 4096; i += 256) {
        int r  = i & 127;
        int c4 = i >> 7;
        float4 v = make_float4(0.f, 0.f, 0.f, 0.f);
        if (row0 + r < N_NODES)
            v = *(const float4*)(A + (size_t)(row0 + r) * HID + (c4 << 2));
        int k = c4 << 2;
        xs[(k + 0) * 132 + r] = v.x;
        xs[(k + 1) * 132 + r] = v.y;
        xs[(k + 2) * 132 + r] = v.z;
        xs[(k + 3) * 132 + r] = v.w;
    }
    // W duplicated pairs
    for (int i = threadIdx.x; i < 4096; i += 256) {
        float4 v = ((const float4*)W)[i];
        int b = i << 2;
        wd[b + 0] = dup2(v.x);
        wd[b + 1] = dup2(v.y);
        wd[b + 2] = dup2(v.z);
        wd[b + 3] = dup2(v.w);
    }
    __syncthreads();

    int tx = threadIdx.x & 15;
    int ty = threadIdx.x >> 4;

    u64 acc[4][8];
#pragma unroll
    for (int i2 = 0; i2 < 4; i2++)
#pragma unroll
        for (int jj = 0; jj < 8; jj++) acc[i2][jj] = 0ull;

    const u64* xsd = (const u64*)xs;             // stride 66 u64 per k

#pragma unroll 4
    for (int k = 0; k < 128; k++) {
        u64 a2[4];
#pragma unroll
        for (int i2 = 0; i2 < 4; i2++)
            a2[i2] = xsd[k * 66 + ty + 16 * i2];
#pragma unroll
        for (int jj = 0; jj < 8; jj++) {
            u64 w2 = wd[(k << 7) + tx + 16 * jj];
#pragma unroll
            for (int i2 = 0; i2 < 4; i2++)
                acc[i2][jj] = fma2(a2[i2], w2, acc[i2][jj]);
        }
    }

    // packed bias add
    u64 bv2[8];
#pragma unroll
    for (int jj = 0; jj < 8; jj++) bv2[jj] = dup2(bias[tx + 16 * jj]);
#pragma unroll
    for (int i2 = 0; i2 < 4; i2++)
#pragma unroll
        for (int jj = 0; jj < 8; jj++) acc[i2][jj] = add2(acc[i2][jj], bv2[jj]);

    // epilogue
#pragma unroll
    for (int i2 = 0; i2 < 4; i2++) {
        int p = ty + 16 * i2;                    // row pair
#pragma unroll
        for (int e = 0; e < 2; e++) {
            int r = row0 + 2 * p + e;
            if (r >= N_NODES) continue;
#pragma unroll
            for (int jj = 0; jj < 8; jj++) {
                unsigned u = (unsigned)(e ? (acc[i2][jj] >> 32)
                                          : (acc[i2][jj] & 0xffffffffull));
                float v = __uint_as_float(u);
                if (act) v = (v > 0.f) ? v : expm1f(v);
                int c = tx + 16 * jj;
                size_t idx = (size_t)r * HID + c;
                C[idx] = v;
                if (do_rep) {
                    uint32_t bits = threefry_bits_0_42(0u, (uint32_t)idx);
                    float eps = bits_to_normal(bits);
                    z_out[idx] = mu_in[idx] + eps * expf(0.5f * v);
                }
            }
        }
    }
}

// ---------------- launch ----------------------------------------------------
extern "C" void kernel_launch(void* const* d_in, const int* in_sizes, int n_in,
                              void* d_out, int out_size) {
    const float* x   = (const float*)d_in[0];
    const int*   ei  = (const int*)d_in[1];
    const float* W1  = (const float*)d_in[2];
    const float* b1  = (const float*)d_in[3];
    const float* Wmu = (const float*)d_in[4];
    const float* bmu = (const float*)d_in[5];
    const float* Wlv = (const float*)d_in[6];
    const float* blv = (const float*)d_in[7];
    float* out = (float*)d_out;

    const int* src = ei;
    const int* dst = ei + N_EDGES;

    void *p_agg, *p_h1, *p_mu, *p_lv;
    cudaGetSymbolAddress(&p_agg, g_agg);
    cudaGetSymbolAddress(&p_h1,  g_h1);
    cudaGetSymbolAddress(&p_mu,  g_mu);
    cudaGetSymbolAddress(&p_lv,  g_lv);

    float* mu_dst = (out_size >= 3 * NH) ? (out + NH)     : (float*)p_mu;
    float* lv_dst = (out_size >= 3 * NH) ? (out + 2 * NH) : (float*)p_lv;

    const size_t gemm_smem = 128 * 132 * sizeof(float) + 128 * 128 * sizeof(u64);
    cudaFuncSetAttribute(k_gemm2, cudaFuncAttributeMaxDynamicSharedMemorySize,
                         (int)gemm_smem);   // 198,656 B

    const int nb_nodes = (N_NODES + 255) / 256;   // 391
    const int nb_edges = (N_EDGES + 255) / 256;   // 6250
    const int nb_agg   = (N_NODES + 7) / 8;       // 12500 (8 warps per block)
    const int nb_gemm  = (N_NODES + 127) / 128;   // 782

    // degree -> dinv, CSR build (shared by both layers)
    k_zero_cnt<<<nb_nodes, 256>>>();
    k_degree<<<nb_edges, 256>>>(dst);
    k_dinv<<<nb_nodes, 256>>>();
    k_scan1<<<nb_nodes, 256>>>();
    k_scan2<<<1, 512>>>();
    k_scan3<<<nb_nodes, 256>>>();
    k_fill<<<nb_edges, 256>>>(src, dst);

    // layer 1: agg = A_norm @ x ; h1 = elu(agg @ W1 + b1)
    k_agg<<<nb_agg, 256>>>(x, (float*)p_agg);
    k_gemm2<<<nb_gemm, 256, gemm_smem>>>((const float*)p_agg, W1, b1,
                                         (float*)p_h1, nullptr, nullptr, 1, 0);

    // layer 2: agg = A_norm @ h1 ; mu ; lv (+fused reparam -> z)
    k_agg<<<nb_agg, 256>>>((const float*)p_h1, (float*)p_agg);
    k_gemm2<<<nb_gemm, 256, gemm_smem>>>((const float*)p_agg, Wmu, bmu,
                                         mu_dst, nullptr, nullptr, 0, 0);
    k_gemm2<<<nb_gemm, 256, gemm_smem>>>((const float*)p_agg, Wlv, blv,
                                         lv_dst, mu_dst, out, 0, 1);
}